// round 8
// baseline (speedup 1.0000x reference)
#include <cuda_runtime.h>
#include <math_constants.h>

#define D_FEAT   128
#define K_NEIGH  32
#define WARPS_PER_CTA 2
// Per-warp stash: 32 rows x 32 float4 = 16 KB. Slot ((p*4+j)*32 + lane)
// (float4 units): STS is lane-contiguous (conflict-free) and the gather read
// pattern covers all 32 banks per 8-lane phase (conflict-free).
#define STASH_F4_PER_WARP (K_NEIGH * (D_FEAT / 4))   // 1024 float4 = 16 KB

// Map float -> uint preserving order (monotone), so integer max == float max.
__device__ __forceinline__ unsigned order_key(float f) {
    unsigned x = __float_as_uint(f);
    return (x & 0x80000000u) ? ~x : (x | 0x80000000u);
}

// One WARP per batch item. The kernel is L2-bandwidth-bound (R3/R6 both sit at
// the ~6300 B/cyc LTS cap), so this version removes the winner re-gather's L2
// traffic (5 KB/item, ~22% of bytes): every neighbor row is stashed in shared
// memory as it is loaded during the sim phase, and the top-ns winner rows are
// read back from smem (crossbar, not L2).
// 2 warps/CTA keeps dynamic smem at 32 KB -- under the 48 KB limit, so no
// cudaFuncSetAttribute is needed in kernel_launch (graph-capture safe).
// Sim math identical to R3 (proven): 4 rows per pass, 8-lane-group butterfly,
// key = dot * rsqrt(||n||^2) (center norm cancels for top-k); exact REDUX
// selection, tie -> lowest index (jax.lax.top_k stability).
__global__ __launch_bounds__(WARPS_PER_CTA * 32, 7)
void intra_agg_kernel(const float*  __restrict__ feats,
                      const int*    __restrict__ nodes,
                      const int*    __restrict__ neighs,
                      const int*    __restrict__ nsamp_p,
                      float*        __restrict__ out)
{
    extern __shared__ float4 s_stash[];   // WARPS_PER_CTA * 1024 float4 = 32 KB

    const int lane = threadIdx.x & 31;
    const int warp = threadIdx.x >> 5;
    const int b    = blockIdx.x * WARPS_PER_CTA + warp;
    const int g    = lane >> 3;        // group 0..3 (which row of the quad)
    const int t    = lane & 7;         // lane within group

    const float4* __restrict__ f4 = reinterpret_cast<const float4*>(feats);
    float4* __restrict__ my_stash = s_stash + warp * STASH_F4_PER_WARP;

    // ---- center row: this lane's 16-float column slice ----
    const int node = nodes[b];
    float4 c[4];
    #pragma unroll
    for (int j = 0; j < 4; j++)
        c[j] = f4[(size_t)node * (D_FEAT / 4) + t + 8 * j];

    // ---- my neighbor index (one coalesced 128B load) ----
    const int my_idx = neighs[b * K_NEIGH + lane];

    // ---- similarities: 8 passes x 4 rows; lane k ends with sim of row k.
    //      Each loaded chunk is also stashed to smem for the gather phase. ----
    float my_sim = 0.0f;
    #pragma unroll
    for (int p = 0; p < K_NEIGH / 4; p++) {
        const int nidx = __shfl_sync(0xffffffffu, my_idx, 4 * p + g);
        const float4* __restrict__ row = f4 + (size_t)nidx * (D_FEAT / 4);

        float dot = 0.0f, ss = 0.0f;
        #pragma unroll
        for (int j = 0; j < 4; j++) {
            const float4 v = row[t + 8 * j];
            my_stash[(p * 4 + j) * 32 + lane] = v;     // conflict-free STS.128
            dot = fmaf(v.x, c[j].x, fmaf(v.y, c[j].y,
                  fmaf(v.z, c[j].z, fmaf(v.w, c[j].w, dot))));
            ss  = fmaf(v.x, v.x, fmaf(v.y, v.y,
                  fmaf(v.z, v.z, fmaf(v.w, v.w, ss))));
        }
        // 3-stage butterfly within each 8-lane group (serves 4 rows at once)
        #pragma unroll
        for (int off = 1; off < 8; off <<= 1) {
            dot += __shfl_xor_sync(0xffffffffu, dot, off);
            ss  += __shfl_xor_sync(0xffffffffu, ss,  off);
        }
        const float s = dot * rsqrtf(ss);
        // route: row 4p+g' was reduced in group g' -> lane 4p+m keeps row 4p+m
        const float sv = __shfl_sync(0xffffffffu, s, (lane & 3) * 8);
        if ((lane >> 2) == p) my_sim = sv;
    }

    __syncwarp(0xffffffffu);   // stash visible to all lanes of this warp

    const int ns = nsamp_p ? *nsamp_p : 10;

    // ---- top-ns selection: record winners into a bitmask first ----
    unsigned u = order_key(my_sim);
    unsigned wmask = 0u;
    for (int i = 0; i < ns; i++) {
        const unsigned m   = __reduce_max_sync(0xffffffffu, u);
        const unsigned msk = __ballot_sync(0xffffffffu, u == m);
        const int      w   = __ffs(msk) - 1;            // tie -> lowest index
        if (lane == w) u = 0u;                          // below any real key
        wmask |= 1u << w;                               // lane w == row w
    }

    // ---- gather winner rows from the smem stash (no L2 traffic) ----
    // Row k chunk l lives at ((k>>2)*4 + (l>>3))*32 + (k&3)*8 + (l&7):
    // for fixed k, the 32 lanes hit 32 distinct banks (conflict-free).
    const int jj = lane >> 3;            // my chunk's j
    const int tt = lane & 7;             // my chunk's t
    float4 acc0 = make_float4(0.f, 0.f, 0.f, 0.f);
    float4 acc1 = make_float4(0.f, 0.f, 0.f, 0.f);
    int i = 0;
    while (wmask) {
        const int k = __ffs(wmask) - 1;
        wmask &= wmask - 1;
        const float4 v =
            my_stash[(((k >> 2) * 4 + jj) * 32) + ((k & 3) * 8 + tt)];
        if (i & 1) { acc1.x += v.x; acc1.y += v.y; acc1.z += v.z; acc1.w += v.w; }
        else       { acc0.x += v.x; acc0.y += v.y; acc0.z += v.z; acc0.w += v.w; }
        i++;
    }

    // ---- mean + relu, coalesced store ----
    const float inv = 1.0f / (float)ns;
    float4 r;
    r.x = fmaxf((acc0.x + acc1.x) * inv, 0.0f);
    r.y = fmaxf((acc0.y + acc1.y) * inv, 0.0f);
    r.z = fmaxf((acc0.z + acc1.z) * inv, 0.0f);
    r.w = fmaxf((acc0.w + acc1.w) * inv, 0.0f);
    reinterpret_cast<float4*>(out)[(size_t)b * (D_FEAT / 4) + lane] = r;
}

extern "C" void kernel_launch(void* const* d_in, const int* in_sizes, int n_in,
                              void* d_out, int out_size)
{
    const float* feats  = (const float*)d_in[0];   // [N_NODES, 128] f32
    const int*   nodes  = (const int*)d_in[1];     // [B] i32
    const int*   neighs = (const int*)d_in[2];     // [B, 32] i32
    const int*   nsamp  = (n_in > 3) ? (const int*)d_in[3] : nullptr;  // scalar (10)

    const int B = in_sizes[1];                     // 32768
    const size_t smem = WARPS_PER_CTA * STASH_F4_PER_WARP * sizeof(float4); // 32 KB
    intra_agg_kernel<<<B / WARPS_PER_CTA, WARPS_PER_CTA * 32, smem>>>(
        feats, nodes, neighs, nsamp, (float*)d_out);
}

// round 9
// speedup vs baseline: 1.6961x; 1.6961x over previous
#include <cuda_runtime.h>
#include <math_constants.h>

#define D_FEAT   128
#define K_NEIGH  32
#define WARPS_PER_CTA 4

// Map float -> uint preserving order (monotone), so integer max == float max.
__device__ __forceinline__ unsigned order_key(float f) {
    unsigned x = __float_as_uint(f);
    return (x & 0x80000000u) ? ~x : (x | 0x80000000u);
}

// One WARP per batch item, no shared memory (R3 structure — the proven
// near-L2-floor configuration; both stash variants regressed).
// Sim phase: 4 rows per pass; warp splits into 4 groups of 8 lanes, each group
// owns one row with 128B-contiguous per-instruction chunks (wavefront-optimal).
// Owner permutation (proven in R6): lane 8g+p keeps sim of row 4p+g, so no
// route shuffle is needed. Exact-sim ties only arise from duplicate neighbor
// indices (identical rows), so owner-lane tie order is output-equivalent to
// jax.lax.top_k's row-order tie-break.
// Ranking key = dot * rsqrt(||n||^2) (center norm cancels for top-k).
// Selection: exact REDUX argmax rounds recorded into a bitmask FIRST; then all
// winner indices are resolved and all ns gathers issue back-to-back (MLP=ns,
// mostly L1/L2-hot) into two accumulator chains.
__global__ __launch_bounds__(WARPS_PER_CTA * 32, 9)
void intra_agg_kernel(const float*  __restrict__ feats,
                      const int*    __restrict__ nodes,
                      const int*    __restrict__ neighs,
                      const int*    __restrict__ nsamp_p,
                      float*        __restrict__ out)
{
    const int lane = threadIdx.x & 31;
    const int warp = threadIdx.x >> 5;
    const int b    = blockIdx.x * WARPS_PER_CTA + warp;
    const int g    = lane >> 3;        // group 0..3 (which row of the quad)
    const int t    = lane & 7;         // lane within group

    const float4* __restrict__ f4 = reinterpret_cast<const float4*>(feats);

    // ---- center row: this lane's 16-float column slice ----
    const int node = nodes[b];
    float4 c[4];
    #pragma unroll
    for (int j = 0; j < 4; j++)
        c[j] = f4[(size_t)node * (D_FEAT / 4) + t + 8 * j];

    // ---- my neighbor index (one coalesced 128B load) ----
    const int my_idx = neighs[b * K_NEIGH + lane];

    // ---- similarities: 8 passes x 4 rows; lane 8g+p keeps sim of row 4p+g ----
    float my_sim = 0.0f;
    #pragma unroll
    for (int p = 0; p < K_NEIGH / 4; p++) {
        const int nidx = __shfl_sync(0xffffffffu, my_idx, 4 * p + g);
        const float4* __restrict__ row = f4 + (size_t)nidx * (D_FEAT / 4);

        float dot = 0.0f, ss = 0.0f;
        #pragma unroll
        for (int j = 0; j < 4; j++) {
            const float4 v = row[t + 8 * j];
            dot = fmaf(v.x, c[j].x, fmaf(v.y, c[j].y,
                  fmaf(v.z, c[j].z, fmaf(v.w, c[j].w, dot))));
            ss  = fmaf(v.x, v.x, fmaf(v.y, v.y,
                  fmaf(v.z, v.z, fmaf(v.w, v.w, ss))));
        }
        // 3-stage butterfly within each 8-lane group (serves 4 rows at once)
        #pragma unroll
        for (int off = 1; off < 8; off <<= 1) {
            dot += __shfl_xor_sync(0xffffffffu, dot, off);
            ss  += __shfl_xor_sync(0xffffffffu, ss,  off);
        }
        if (t == p) my_sim = dot * rsqrtf(ss);   // owner lane 8g+p <- row 4p+g
    }

    const int ns = nsamp_p ? *nsamp_p : 10;

    // ---- top-ns selection: record winner OWNER lanes into a bitmask ----
    unsigned u = order_key(my_sim);
    unsigned wmask = 0u;
    for (int i = 0; i < ns; i++) {
        const unsigned m   = __reduce_max_sync(0xffffffffu, u);
        const unsigned msk = __ballot_sync(0xffffffffu, u == m);
        const int      w   = __ffs(msk) - 1;            // tie -> duplicate row
        if (lane == w) u = 0u;                          // below any real key
        wmask |= 1u << w;
    }

    // ---- resolve winner node indices, then batch all gathers (MLP=ns) ----
    float4 acc0 = make_float4(0.f, 0.f, 0.f, 0.f);
    float4 acc1 = make_float4(0.f, 0.f, 0.f, 0.f);
    if (ns == 10) {                       // fast path: fully unrolled batch
        int nn[10];
        unsigned wm = wmask;
        #pragma unroll
        for (int i = 0; i < 10; i++) {
            const int w = __ffs(wm) - 1;
            wm &= wm - 1;
            const int r = 4 * (w & 7) + (w >> 3);       // owner lane -> row
            nn[i] = __shfl_sync(0xffffffffu, my_idx, r);
        }
        #pragma unroll
        for (int i = 0; i < 10; i++) {
            const float4 v = f4[(size_t)nn[i] * (D_FEAT / 4) + lane];
            if (i & 1) { acc1.x += v.x; acc1.y += v.y; acc1.z += v.z; acc1.w += v.w; }
            else       { acc0.x += v.x; acc0.y += v.y; acc0.z += v.z; acc0.w += v.w; }
        }
    } else {
        int i = 0;
        while (wmask) {
            const int w = __ffs(wmask) - 1;
            wmask &= wmask - 1;
            const int r = 4 * (w & 7) + (w >> 3);
            const int nnid = __shfl_sync(0xffffffffu, my_idx, r);
            const float4 v = f4[(size_t)nnid * (D_FEAT / 4) + lane];
            if (i & 1) { acc1.x += v.x; acc1.y += v.y; acc1.z += v.z; acc1.w += v.w; }
            else       { acc0.x += v.x; acc0.y += v.y; acc0.z += v.z; acc0.w += v.w; }
            i++;
        }
    }

    // ---- mean + relu, coalesced store ----
    const float inv = 1.0f / (float)ns;
    float4 r;
    r.x = fmaxf((acc0.x + acc1.x) * inv, 0.0f);
    r.y = fmaxf((acc0.y + acc1.y) * inv, 0.0f);
    r.z = fmaxf((acc0.z + acc1.z) * inv, 0.0f);
    r.w = fmaxf((acc0.w + acc1.w) * inv, 0.0f);
    reinterpret_cast<float4*>(out)[(size_t)b * (D_FEAT / 4) + lane] = r;
}

extern "C" void kernel_launch(void* const* d_in, const int* in_sizes, int n_in,
                              void* d_out, int out_size)
{
    const float* feats  = (const float*)d_in[0];   // [N_NODES, 128] f32
    const int*   nodes  = (const int*)d_in[1];     // [B] i32
    const int*   neighs = (const int*)d_in[2];     // [B, 32] i32
    const int*   nsamp  = (n_in > 3) ? (const int*)d_in[3] : nullptr;  // scalar (10)

    const int B = in_sizes[1];                     // 32768
    intra_agg_kernel<<<B / WARPS_PER_CTA, WARPS_PER_CTA * 32>>>(
        feats, nodes, neighs, nsamp, (float*)d_out);
}